// round 3
// baseline (speedup 1.0000x reference)
#include <cuda_runtime.h>
#include <cstdint>

#define NBLK  4
#define NBATCH 128
#define KD    1024
#define NO    4096

// ---------------- scratch (device globals; no allocation) ----------------
__device__ int8_t g_wih[(size_t)NBLK * NO * KD];     // quantized W_ih^T  [n][o][i]
__device__ int8_t g_whh[(size_t)NBLK * NO * KD];     // quantized (W_hh*mask)^T [n][o][i]
__device__ int8_t g_qx [(size_t)NBLK * NBATCH * KD]; // quantized input   [n][b][i]
__device__ int8_t g_qh [(size_t)NBLK * NBATCH * KD]; // quantized hx      [n][b][i]
__device__ float  g_gates[(size_t)NBLK * NBATCH * NO];

// ---------------- reference-faithful scalar math ----------------
// pact(x,a) = sign(x)*0.5*((|x| - ||x|-a|) + a), computed with the same fp32 op
// order as the reference (NOT simplified to clamp: the fp rounding differs).
__device__ __forceinline__ float pactf(float x, float a) {
    float sg = (x > 0.0f) ? 1.0f : ((x < 0.0f) ? -1.0f : 0.0f);
    float ax = fabsf(x);
    return sg * (0.5f * ((ax - fabsf(ax - a)) + a));
}
__device__ __forceinline__ float clip01(float u) {
    // clip to [-1+1/128, 1-1/128] (exact fp32 constants)
    return fminf(fmaxf(u, -0.9921875f), 0.9921875f);
}
// integer code q = round(clip(pact(x,a)/a)*128) in [-127,127]
__device__ __forceinline__ int qint(float x, float a) {
    float u = __fdiv_rn(pactf(x, a), a);   // IEEE div even under fast-math
    return (int)rintf(clip01(u) * 128.0f); // rintf = round-half-even (jnp.round)
}
// fake-quant value: (q/128)*a, matching qp(pact(x,a), 8, a)
__device__ __forceinline__ float qvalf(float x, float a) {
    float u = __fdiv_rn(pactf(x, a), a);
    float q = rintf(clip01(u) * 128.0f);
    return (q * 0.0078125f) * a;
}

// ---------------- kernel 1: quantize activations ----------------
__global__ __launch_bounds__(256) void k_qact(
    const float* __restrict__ x, const float* __restrict__ hx,
    const float* __restrict__ a1v, const float* __restrict__ a11v)
{
    int idx = blockIdx.x * 256 + threadIdx.x;      // one char4 per thread
    const int total = NBLK * NBATCH * KD / 4;      // 131072
    if (idx >= total) return;
    int e   = idx * 4;
    int n   = e >> 17;                  // BATCH*KD = 131072 per block
    int rem = e & 131071;               // b*KD + i
    float A1  = a1v[n];
    float A11 = a11v[n];
    const float* xp = x + rem;          // x broadcast across n
    const float* hp = hx + (size_t)n * (NBATCH * KD) + rem;
    char4 cx4, ch4;
    cx4.x = (char)qint(xp[0], A1);  cx4.y = (char)qint(xp[1], A1);
    cx4.z = (char)qint(xp[2], A1);  cx4.w = (char)qint(xp[3], A1);
    ch4.x = (char)qint(hp[0], A11); ch4.y = (char)qint(hp[1], A11);
    ch4.z = (char)qint(hp[2], A11); ch4.w = (char)qint(hp[3], A11);
    *reinterpret_cast<char4*>(g_qx + e) = cx4;
    *reinterpret_cast<char4*>(g_qh + e) = ch4;
}

// ---------------- kernel 2: quantize + transpose weights ----------------
// Reads W[n][i][o] fp32 coalesced along o; writes int8 W^T[n][o][i] coalesced
// along i (char4). SMEM 32x132 byte tile (pad 4 => conflict-free both phases).
__global__ __launch_bounds__(256) void k_qw(
    const float* __restrict__ wih, const float* __restrict__ whh,
    const float* __restrict__ wmask)
{
    __shared__ char tile[32 * 132];
    int n  = blockIdx.z;
    int i0 = blockIdx.y * 128;
    int o0 = blockIdx.x * 32;
    int t  = threadIdx.x;
    int oo = t & 31, ib = t >> 5;
    size_t srcoff = ((size_t)n * KD + i0) * NO + o0 + oo;

    // ----- weight_ih: clip(w,±1) then clip(.,±127/128) == clip(w,±127/128)
    #pragma unroll
    for (int s = 0; s < 16; s++) {
        int i = ib + 8 * s;
        float w = wih[srcoff + (size_t)i * NO];
        w = fminf(fmaxf(w, -0.9921875f), 0.9921875f);
        tile[oo * 132 + i] = (char)(int)rintf(w * 128.0f);
    }
    __syncthreads();
    {
        int8_t* dst = g_wih + ((size_t)n * NO + o0) * KD + i0;
        #pragma unroll
        for (int p = 0; p < 4; p++) {
            int c4 = t + 256 * p;
            int o  = c4 >> 5;
            int i4 = (c4 & 31) * 4;
            char4 v;
            v.x = tile[o * 132 + i4];     v.y = tile[o * 132 + i4 + 1];
            v.z = tile[o * 132 + i4 + 2]; v.w = tile[o * 132 + i4 + 3];
            *reinterpret_cast<char4*>(dst + (size_t)o * KD + i4) = v;
        }
    }
    __syncthreads();

    // ----- weight_hh * w_mask
    #pragma unroll
    for (int s = 0; s < 16; s++) {
        int i = ib + 8 * s;
        size_t a = srcoff + (size_t)i * NO;
        float w = whh[a] * wmask[a];
        w = fminf(fmaxf(w, -0.9921875f), 0.9921875f);
        tile[oo * 132 + i] = (char)(int)rintf(w * 128.0f);
    }
    __syncthreads();
    {
        int8_t* dst = g_whh + ((size_t)n * NO + o0) * KD + i0;
        #pragma unroll
        for (int p = 0; p < 4; p++) {
            int c4 = t + 256 * p;
            int o  = c4 >> 5;
            int i4 = (c4 & 31) * 4;
            char4 v;
            v.x = tile[o * 132 + i4];     v.y = tile[o * 132 + i4 + 1];
            v.z = tile[o * 132 + i4 + 2]; v.w = tile[o * 132 + i4 + 3];
            *reinterpret_cast<char4*>(dst + (size_t)o * KD + i4) = v;
        }
    }
}

// ---------------- kernel 3: dual int8 GEMM + gate epilogue ----------------
__device__ __forceinline__ void cp16(char* s, const void* g) {
    unsigned sa = (unsigned)__cvta_generic_to_shared(s);
    asm volatile("cp.async.cg.shared.global [%0], [%1], 16;" :: "r"(sa), "l"(g));
}
__device__ __forceinline__ void imma8(int* c, const unsigned* a, const unsigned* b) {
    asm volatile(
        "mma.sync.aligned.m16n8k32.row.col.s32.s8.s8.s32 "
        "{%0,%1,%2,%3}, {%4,%5,%6,%7}, {%8,%9}, {%0,%1,%2,%3};"
        : "+r"(c[0]), "+r"(c[1]), "+r"(c[2]), "+r"(c[3])
        : "r"(a[0]), "r"(a[1]), "r"(a[2]), "r"(a[3]), "r"(b[0]), "r"(b[1]));
}

// SMEM stage: A rows stride 48B (conflict-free for the frag pattern: (12r+c)%32
// covers all banks), K-chunk = 32 (one k-step per chunk), double buffered.
#define ST_A1 0
#define ST_A2 6144
#define ST_B1 12288
#define ST_B2 13824
#define STAGE 15360

__global__ __launch_bounds__(256) void k_gemm(
    const float* __restrict__ bih, const float* __restrict__ bhh,
    const float* __restrict__ a1v,  const float* __restrict__ a11v,
    const float* __restrict__ a12v, const float* __restrict__ a13v,
    const float* __restrict__ a14v)
{
    __shared__ char smem[2 * STAGE];
    int n  = blockIdx.z;
    int o0 = blockIdx.x * 32;                 // CTA tile: 128 x 32
    int t  = threadIdx.x, lane = t & 31, wid = t >> 5;
    int wm = wid >> 1, wn = wid & 1;          // warp tile: m32 x n16

    const int8_t* gA1 = g_qx  + (size_t)n * NBATCH * KD;
    const int8_t* gA2 = g_qh  + (size_t)n * NBATCH * KD;
    const int8_t* gB1 = g_wih + ((size_t)n * NO + o0) * KD;
    const int8_t* gB2 = g_whh + ((size_t)n * NO + o0) * KD;

    int acc1[2][2][4], acc2[2][2][4];
    #pragma unroll
    for (int a = 0; a < 2; a++)
        #pragma unroll
        for (int b = 0; b < 2; b++)
            #pragma unroll
            for (int c = 0; c < 4; c++) { acc1[a][b][c] = 0; acc2[a][b][c] = 0; }

    int rA = t >> 1, hA = (t & 1) * 16;

    auto stage_copy = [&](int s, int k0) {
        char* base = smem + s * STAGE;
        cp16(base + ST_A1 + rA * 48 + hA, gA1 + (size_t)rA * KD + k0 + hA);
        cp16(base + ST_A2 + rA * 48 + hA, gA2 + (size_t)rA * KD + k0 + hA);
        if (t < 64) {
            int rb = t >> 1, hb = (t & 1) * 16;
            cp16(base + ST_B1 + rb * 48 + hb, gB1 + (size_t)rb * KD + k0 + hb);
        } else if (t < 128) {
            int tt = t - 64; int rb = tt >> 1, hb = (tt & 1) * 16;
            cp16(base + ST_B2 + rb * 48 + hb, gB2 + (size_t)rb * KD + k0 + hb);
        }
        asm volatile("cp.async.commit_group;");
    };

    stage_copy(0, 0);
    const int NK = KD / 32;
    for (int kk = 0; kk < NK; kk++) {
        int s = kk & 1;
        if (kk + 1 < NK) {
            stage_copy(s ^ 1, (kk + 1) * 32);
            asm volatile("cp.async.wait_group 1;");
        } else {
            asm volatile("cp.async.wait_group 0;");
        }
        __syncthreads();

        const char* base = smem + s * STAGE;
        int c  = lane & 3;
        int rq = lane >> 2;
        unsigned a1f[2][4], a2f[2][4], b1f[2][2], b2f[2][2];
        #pragma unroll
        for (int mi = 0; mi < 2; mi++) {
            int r = wm * 32 + mi * 16 + rq;
            const unsigned* p0 = (const unsigned*)(base + ST_A1 + r * 48);
            const unsigned* p8 = (const unsigned*)(base + ST_A1 + (r + 8) * 48);
            a1f[mi][0] = p0[c]; a1f[mi][1] = p8[c];
            a1f[mi][2] = p0[c + 4]; a1f[mi][3] = p8[c + 4];
            const unsigned* q0 = (const unsigned*)(base + ST_A2 + r * 48);
            const unsigned* q8 = (const unsigned*)(base + ST_A2 + (r + 8) * 48);
            a2f[mi][0] = q0[c]; a2f[mi][1] = q8[c];
            a2f[mi][2] = q0[c + 4]; a2f[mi][3] = q8[c + 4];
        }
        #pragma unroll
        for (int ni = 0; ni < 2; ni++) {
            int nn = wn * 16 + ni * 8 + rq;
            const unsigned* pb = (const unsigned*)(base + ST_B1 + nn * 48);
            b1f[ni][0] = pb[c]; b1f[ni][1] = pb[c + 4];
            const unsigned* qb = (const unsigned*)(base + ST_B2 + nn * 48);
            b2f[ni][0] = qb[c]; b2f[ni][1] = qb[c + 4];
        }
        #pragma unroll
        for (int mi = 0; mi < 2; mi++)
            #pragma unroll
            for (int ni = 0; ni < 2; ni++) {
                imma8(acc1[mi][ni], a1f[mi], b1f[ni]);
                imma8(acc2[mi][ni], a2f[mi], b2f[ni]);
            }
        __syncthreads();
    }

    // epilogue: exact scales (powers of 2 => exact fp32), bias quant, gate quant
    float S1  = a1v[n]  * (1.0f / 16384.0f);
    float S2  = a11v[n] * (1.0f / 16384.0f);
    float A12 = a12v[n], A13 = a13v[n], A14 = a14v[n];

    // hoist bias quantization: each thread touches 8 distinct columns
    // col(ni, p) = o0 + wn*16 + ni*8 + (lane&3)*2 + p
    float qb1c[2][2], qb2c[2][2];
    #pragma unroll
    for (int ni = 0; ni < 2; ni++)
        #pragma unroll
        for (int p = 0; p < 2; p++) {
            int col = o0 + wn * 16 + ni * 8 + (lane & 3) * 2 + p;
            float bv1 = bih[n * NO + col];
            bv1 = fminf(fmaxf(bv1, -0.9921875f), 0.9921875f);
            qb1c[ni][p] = rintf(bv1 * 128.0f) * 0.0078125f;
            float bv2 = bhh[n * NO + col];
            bv2 = fminf(fmaxf(bv2, -0.9921875f), 0.9921875f);
            qb2c[ni][p] = rintf(bv2 * 128.0f) * 0.0078125f;
        }

    #pragma unroll
    for (int mi = 0; mi < 2; mi++)
        #pragma unroll
        for (int ni = 0; ni < 2; ni++)
            #pragma unroll
            for (int e = 0; e < 4; e++) {
                int row = wm * 32 + mi * 16 + (lane >> 2) + ((e >> 1) << 3);
                int col = o0 + wn * 16 + ni * 8 + (lane & 3) * 2 + (e & 1);
                float p1 = (float)acc1[mi][ni][e] * S1 + qb1c[ni][e & 1];
                float p2 = (float)acc2[mi][ni][e] * S2 + qb2c[ni][e & 1];
                float v  = qvalf(p1, A12) + qvalf(p2, A13);
                g_gates[((size_t)n * NBATCH + row) * NO + col] = qvalf(v, A14);
            }
}

// ---------------- kernel 4: elementwise LSTM tail (2 elems/thread) ----------------
__global__ __launch_bounds__(256) void k_lstm(
    const float* __restrict__ cx, float* __restrict__ out,
    const float* a3,  const float* a4,  const float* a5, const float* a6,
    const float* a7,  const float* a8,  const float* a9, const float* a10,
    const float* a11)
{
    const int total = NBLK * NBATCH * KD;   // 524288
    int idx0 = (blockIdx.x * 256 + threadIdx.x) * 2;
    if (idx0 >= total) return;
    int n   = idx0 >> 17;
    int rem = idx0 & 131071;
    int b   = rem >> 10, h = rem & 1023;
    const float* gp = g_gates + ((size_t)n * NBATCH + b) * NO;

    float A3 = a3[n], A4 = a4[n], A5 = a5[n], A6 = a6[n], A7 = a7[n];
    float A8 = a8[n], A9 = a9[n], A10 = a10[n], A11 = a11[n];

    #pragma unroll
    for (int u = 0; u < 2; u++) {
        int idx = idx0 + u;
        int hh  = h + u;
        float gi = gp[hh];
        float gj = gp[KD + hh];
        float gf = gp[2 * KD + hh];
        float go = gp[3 * KD + hh];

        float fg = qvalf(1.0f / (1.0f + expf(-gf)), A3);
        float ig = qvalf(1.0f / (1.0f + expf(-gi)), A4);
        float ac = qvalf(tanhf(gj),                 A5);
        float og = qvalf(1.0f / (1.0f + expf(-go)), A6);

        float gc = qvalf(cx[idx] * fg, A7);
        float ai = qvalf(ig * ac,      A8);
        float nc = qvalf(gc + ai,      A9);
        float tc = qvalf(tanhf(nc),    A10);
        float nh = qvalf(tc * og,      A11);

        out[idx]         = nh;  // new_h
        out[total + idx] = nc;  // new_c
    }
}

// ---------------- launcher ----------------
extern "C" void kernel_launch(void* const* d_in, const int* in_sizes, int n_in,
                              void* d_out, int out_size)
{
    const float* input = (const float*)d_in[0];
    const float* hx    = (const float*)d_in[1];
    const float* cx    = (const float*)d_in[2];
    const float* wmask = (const float*)d_in[3];
    const float* wih   = (const float*)d_in[4];
    const float* whh   = (const float*)d_in[5];
    const float* bih   = (const float*)d_in[6];
    const float* bhh   = (const float*)d_in[7];
    const float* a1  = (const float*)d_in[8];
    const float* a3  = (const float*)d_in[9];
    const float* a4  = (const float*)d_in[10];
    const float* a5  = (const float*)d_in[11];
    const float* a6  = (const float*)d_in[12];
    const float* a7  = (const float*)d_in[13];
    const float* a8  = (const float*)d_in[14];
    const float* a9  = (const float*)d_in[15];
    const float* a10 = (const float*)d_in[16];
    const float* a11 = (const float*)d_in[17];
    const float* a12 = (const float*)d_in[18];
    const float* a13 = (const float*)d_in[19];
    const float* a14 = (const float*)d_in[20];
    float* out = (float*)d_out;

    k_qact<<<(NBLK * NBATCH * KD / 4 + 255) / 256, 256>>>(input, hx, a1, a11);

    dim3 gq(NO / 32, KD / 128, NBLK);
    k_qw<<<gq, 256>>>(wih, whh, wmask);

    dim3 gg(NO / 32, 1, NBLK);
    k_gemm<<<gg, 256>>>(bih, bhh, a1, a11, a12, a13, a14);

    k_lstm<<<(NBLK * NBATCH * KD / 2 + 255) / 256, 256>>>(
        cx, out, a3, a4, a5, a6, a7, a8, a9, a10, a11);
}

// round 4
// speedup vs baseline: 1.2905x; 1.2905x over previous
#include <cuda_runtime.h>
#include <cstdint>

#define NBLK  4
#define NBATCH 128
#define KD    1024
#define NO    4096

// ---------------- scratch (device globals; no allocation) ----------------
__device__ int8_t g_qx [(size_t)NBLK * NBATCH * KD]; // quantized input   [n][b][i]
__device__ int8_t g_qh [(size_t)NBLK * NBATCH * KD]; // quantized hx      [n][b][i]
__device__ float  g_gates[(size_t)NBLK * NBATCH * NO];

// ---------------- reference-faithful scalar math ----------------
// pact(x,a) = sign(x)*0.5*((|x| - ||x|-a|) + a), same fp32 op order as reference.
__device__ __forceinline__ float pactf(float x, float a) {
    float sg = (x > 0.0f) ? 1.0f : ((x < 0.0f) ? -1.0f : 0.0f);
    float ax = fabsf(x);
    return sg * (0.5f * ((ax - fabsf(ax - a)) + a));
}
__device__ __forceinline__ float clip01(float u) {
    return fminf(fmaxf(u, -0.9921875f), 0.9921875f);
}
// All a-scales are powers of two => __frcp_rn(a) is exact and x*r == x/a bitwise.
__device__ __forceinline__ int qint_r(float x, float a, float r) {
    float u = pactf(x, a) * r;
    return (int)rintf(clip01(u) * 128.0f);   // rintf = round-half-even (jnp.round)
}
__device__ __forceinline__ float qvalf_r(float x, float a, float r) {
    float u = pactf(x, a) * r;
    float q = rintf(clip01(u) * 128.0f);
    return (q * 0.0078125f) * a;
}

// ---------------- kernel 1: quantize activations ----------------
__global__ __launch_bounds__(256) void k_qact(
    const float* __restrict__ x, const float* __restrict__ hx,
    const float* __restrict__ a1v, const float* __restrict__ a11v)
{
    int idx = blockIdx.x * 256 + threadIdx.x;      // one char4 per thread
    const int total = NBLK * NBATCH * KD / 4;      // 131072
    if (idx >= total) return;
    int e   = idx * 4;
    int n   = e >> 17;                  // BATCH*KD = 131072 per block
    int rem = e & 131071;               // b*KD + i
    float A1  = a1v[n],  R1  = __frcp_rn(A1);
    float A11 = a11v[n], R11 = __frcp_rn(A11);
    const float* xp = x + rem;          // x broadcast across n
    const float* hp = hx + (size_t)n * (NBATCH * KD) + rem;
    char4 cx4, ch4;
    cx4.x = (char)qint_r(xp[0], A1, R1);  cx4.y = (char)qint_r(xp[1], A1, R1);
    cx4.z = (char)qint_r(xp[2], A1, R1);  cx4.w = (char)qint_r(xp[3], A1, R1);
    ch4.x = (char)qint_r(hp[0], A11, R11); ch4.y = (char)qint_r(hp[1], A11, R11);
    ch4.z = (char)qint_r(hp[2], A11, R11); ch4.w = (char)qint_r(hp[3], A11, R11);
    *reinterpret_cast<char4*>(g_qx + e) = cx4;
    *reinterpret_cast<char4*>(g_qh + e) = ch4;
}

// ---------------- kernel 2: fused dual int8 GEMM with in-flight weight quant ----
__device__ __forceinline__ void cp16(char* s, const void* g) {
    unsigned sa = (unsigned)__cvta_generic_to_shared(s);
    asm volatile("cp.async.cg.shared.global [%0], [%1], 16;" :: "r"(sa), "l"(g));
}
__device__ __forceinline__ void imma8(int* c, const unsigned* a, const unsigned* b) {
    asm volatile(
        "mma.sync.aligned.m16n8k32.row.col.s32.s8.s8.s32 "
        "{%0,%1,%2,%3}, {%4,%5,%6,%7}, {%8,%9}, {%0,%1,%2,%3};"
        : "+r"(c[0]), "+r"(c[1]), "+r"(c[2]), "+r"(c[3])
        : "r"(a[0]), "r"(a[1]), "r"(a[2]), "r"(a[3]), "r"(b[0]), "r"(b[1]));
}
// quantize one fp32 weight (already mask-multiplied) to int8 code
__device__ __forceinline__ unsigned qw8(float w) {
    w = fminf(fmaxf(w, -0.9921875f), 0.9921875f);
    return (unsigned)((int)rintf(w * 128.0f)) & 0xFF;
}
// pack 4 weights (ascending o) into one word, bytes little-endian
__device__ __forceinline__ unsigned qw_pack(float4 v) {
    return qw8(v.x) | (qw8(v.y) << 8) | (qw8(v.z) << 16) | (qw8(v.w) << 24);
}

// A stage: rows stride 48B (conflict-free for frag pattern), 32B K-chunk,
// double buffered. B int8 tiles produced per-chunk in smem (single buffer).
#define ST_A1 0
#define ST_A2 6144
#define ASTAGE 12288
#define SM_BQ1 (2 * ASTAGE)
#define SM_BQ2 (2 * ASTAGE + 1536)
#define SM_TOT (2 * ASTAGE + 3072)

__global__ __launch_bounds__(256) void k_gemm(
    const float* __restrict__ wih, const float* __restrict__ whh,
    const float* __restrict__ wmask,
    const float* __restrict__ bih, const float* __restrict__ bhh,
    const float* __restrict__ a1v,  const float* __restrict__ a11v,
    const float* __restrict__ a12v, const float* __restrict__ a13v,
    const float* __restrict__ a14v)
{
    __shared__ char smem[SM_TOT];
    int n  = blockIdx.z;
    int o0 = blockIdx.x * 32;                 // CTA tile: 128 x 32
    int t  = threadIdx.x, lane = t & 31, wid = t >> 5;
    int wm = wid >> 1, wn = wid & 1;          // warp tile: m32 x n16

    const int8_t* gA1 = g_qx + (size_t)n * NBATCH * KD;
    const int8_t* gA2 = g_qh + (size_t)n * NBATCH * KD;
    const float*  gW1 = wih   + (size_t)n * KD * NO + o0;
    const float*  gW2 = whh   + (size_t)n * KD * NO + o0;
    const float*  gM  = wmask + (size_t)n * KD * NO + o0;

    int acc1[2][2][4], acc2[2][2][4];
    #pragma unroll
    for (int a = 0; a < 2; a++)
        #pragma unroll
        for (int b = 0; b < 2; b++)
            #pragma unroll
            for (int c = 0; c < 4; c++) { acc1[a][b][c] = 0; acc2[a][b][c] = 0; }

    // weight-quant thread mapping: i_local = 4*warp + (lane>>3), o-quad = 4*(lane&7)
    int iloc = 4 * wid + (lane >> 3);
    int oq   = 4 * (lane & 7);
    int rsel = lane >> 3;                         // which byte of each word
    unsigned sel01 = (unsigned)(rsel | ((rsel + 4) << 4));
    int orow = oq + rsel;                         // destination int8 row (o within tile)

    int rA = t >> 1, hA = (t & 1) * 16;
    auto stage_copyA = [&](int s, int k0) {
        char* base = smem + s * ASTAGE;
        cp16(base + ST_A1 + rA * 48 + hA, gA1 + (size_t)rA * KD + k0 + hA);
        cp16(base + ST_A2 + rA * 48 + hA, gA2 + (size_t)rA * KD + k0 + hA);
        asm volatile("cp.async.commit_group;");
    };

    // prefetch chunk 0 weights
    float4 cw1 = *(const float4*)(gW1 + (size_t)iloc * NO + oq);
    float4 cw2 = *(const float4*)(gW2 + (size_t)iloc * NO + oq);
    float4 cm  = *(const float4*)(gM  + (size_t)iloc * NO + oq);

    stage_copyA(0, 0);
    const int NK = KD / 32;
    for (int kk = 0; kk < NK; kk++) {
        int s = kk & 1;
        if (kk + 1 < NK) {
            stage_copyA(s ^ 1, (kk + 1) * 32);
            asm volatile("cp.async.wait_group 1;");
        } else {
            asm volatile("cp.async.wait_group 0;");
        }

        // prefetch next chunk's weights (clamped; value unused on last iter)
        int kn = (kk + 1 < NK) ? (kk + 1) : kk;
        size_t nwoff = (size_t)(kn * 32 + iloc) * NO + oq;
        float4 nw1 = *(const float4*)(gW1 + nwoff);
        float4 nw2 = *(const float4*)(gW2 + nwoff);
        float4 nm  = *(const float4*)(gM  + nwoff);

        // quantize current chunk: 4 o's for one i per thread -> packed word
        unsigned W1 = qw_pack(cw1);
        float4 p2 = make_float4(cw2.x * cm.x, cw2.y * cm.y, cw2.z * cm.z, cw2.w * cm.w);
        unsigned W2 = qw_pack(p2);

        // 4x4 byte transpose within lane group {c, c+8, c+16, c+24}
        int c8 = lane & 7;
        unsigned w0 = __shfl_sync(0xFFFFFFFFu, W1, c8);
        unsigned w1 = __shfl_sync(0xFFFFFFFFu, W1, c8 + 8);
        unsigned w2 = __shfl_sync(0xFFFFFFFFu, W1, c8 + 16);
        unsigned w3 = __shfl_sync(0xFFFFFFFFu, W1, c8 + 24);
        unsigned lo = __byte_perm(w0, w1, sel01);
        unsigned hi = __byte_perm(w2, w3, sel01);
        unsigned r1 = __byte_perm(lo, hi, 0x5410);   // [i,i+1,i+2,i+3] for o=orow
        unsigned v0 = __shfl_sync(0xFFFFFFFFu, W2, c8);
        unsigned v1 = __shfl_sync(0xFFFFFFFFu, W2, c8 + 8);
        unsigned v2 = __shfl_sync(0xFFFFFFFFu, W2, c8 + 16);
        unsigned v3 = __shfl_sync(0xFFFFFFFFu, W2, c8 + 24);
        unsigned lo2 = __byte_perm(v0, v1, sel01);
        unsigned hi2 = __byte_perm(v2, v3, sel01);
        unsigned r2 = __byte_perm(lo2, hi2, 0x5410);

        *(unsigned*)(smem + SM_BQ1 + orow * 48 + 4 * wid) = r1;
        *(unsigned*)(smem + SM_BQ2 + orow * 48 + 4 * wid) = r2;

        cw1 = nw1; cw2 = nw2; cm = nm;

        __syncthreads();   // A stage s visible + Bq tiles complete

        const char* base = smem + s * ASTAGE;
        int c  = lane & 3;
        int rq = lane >> 2;
        unsigned a1f[2][4], a2f[2][4], b1f[2][2], b2f[2][2];
        #pragma unroll
        for (int mi = 0; mi < 2; mi++) {
            int r = wm * 32 + mi * 16 + rq;
            const unsigned* p0 = (const unsigned*)(base + ST_A1 + r * 48);
            const unsigned* p8 = (const unsigned*)(base + ST_A1 + (r + 8) * 48);
            a1f[mi][0] = p0[c]; a1f[mi][1] = p8[c];
            a1f[mi][2] = p0[c + 4]; a1f[mi][3] = p8[c + 4];
            const unsigned* q0 = (const unsigned*)(base + ST_A2 + r * 48);
            const unsigned* q8 = (const unsigned*)(base + ST_A2 + (r + 8) * 48);
            a2f[mi][0] = q0[c]; a2f[mi][1] = q8[c];
            a2f[mi][2] = q0[c + 4]; a2f[mi][3] = q8[c + 4];
        }
        #pragma unroll
        for (int ni = 0; ni < 2; ni++) {
            int nn = wn * 16 + ni * 8 + rq;
            const unsigned* pb = (const unsigned*)(smem + SM_BQ1 + nn * 48);
            b1f[ni][0] = pb[c]; b1f[ni][1] = pb[c + 4];
            const unsigned* qb = (const unsigned*)(smem + SM_BQ2 + nn * 48);
            b2f[ni][0] = qb[c]; b2f[ni][1] = qb[c + 4];
        }
        #pragma unroll
        for (int mi = 0; mi < 2; mi++)
            #pragma unroll
            for (int ni = 0; ni < 2; ni++) {
                imma8(acc1[mi][ni], a1f[mi], b1f[ni]);
                imma8(acc2[mi][ni], a2f[mi], b2f[ni]);
            }
        __syncthreads();   // protect Bq + A stage reuse
    }

    // epilogue: exact scales (powers of 2), bias quant, gate quant
    float S1  = a1v[n]  * (1.0f / 16384.0f);
    float S2  = a11v[n] * (1.0f / 16384.0f);
    float A12 = a12v[n], R12 = __frcp_rn(A12);
    float A13 = a13v[n], R13 = __frcp_rn(A13);
    float A14 = a14v[n], R14 = __frcp_rn(A14);

    float qb1c[2][2], qb2c[2][2];
    #pragma unroll
    for (int ni = 0; ni < 2; ni++)
        #pragma unroll
        for (int p = 0; p < 2; p++) {
            int col = o0 + wn * 16 + ni * 8 + (lane & 3) * 2 + p;
            float bv1 = bih[n * NO + col];
            bv1 = fminf(fmaxf(bv1, -0.9921875f), 0.9921875f);
            qb1c[ni][p] = rintf(bv1 * 128.0f) * 0.0078125f;
            float bv2 = bhh[n * NO + col];
            bv2 = fminf(fmaxf(bv2, -0.9921875f), 0.9921875f);
            qb2c[ni][p] = rintf(bv2 * 128.0f) * 0.0078125f;
        }

    #pragma unroll
    for (int mi = 0; mi < 2; mi++)
        #pragma unroll
        for (int ni = 0; ni < 2; ni++)
            #pragma unroll
            for (int e = 0; e < 4; e++) {
                int row = wm * 32 + mi * 16 + (lane >> 2) + ((e >> 1) << 3);
                int col = o0 + wn * 16 + ni * 8 + (lane & 3) * 2 + (e & 1);
                float p1 = (float)acc1[mi][ni][e] * S1 + qb1c[ni][e & 1];
                float p2 = (float)acc2[mi][ni][e] * S2 + qb2c[ni][e & 1];
                float v  = qvalf_r(p1, A12, R12) + qvalf_r(p2, A13, R13);
                g_gates[((size_t)n * NBATCH + row) * NO + col] = qvalf_r(v, A14, R14);
            }
}

// ---------------- kernel 3: elementwise LSTM tail (2 elems/thread) ----------------
__global__ __launch_bounds__(256) void k_lstm(
    const float* __restrict__ cx, float* __restrict__ out,
    const float* a3,  const float* a4,  const float* a5, const float* a6,
    const float* a7,  const float* a8,  const float* a9, const float* a10,
    const float* a11)
{
    const int total = NBLK * NBATCH * KD;   // 524288
    int idx0 = (blockIdx.x * 256 + threadIdx.x) * 2;
    if (idx0 >= total) return;
    int n   = idx0 >> 17;
    int rem = idx0 & 131071;
    int b   = rem >> 10, h = rem & 1023;
    const float* gp = g_gates + ((size_t)n * NBATCH + b) * NO;

    float A3 = a3[n], A4 = a4[n], A5 = a5[n], A6 = a6[n], A7 = a7[n];
    float A8 = a8[n], A9 = a9[n], A10 = a10[n], A11 = a11[n];
    float R3 = __frcp_rn(A3), R4 = __frcp_rn(A4), R5 = __frcp_rn(A5);
    float R6 = __frcp_rn(A6), R7 = __frcp_rn(A7), R8 = __frcp_rn(A8);
    float R9 = __frcp_rn(A9), R10 = __frcp_rn(A10), R11 = __frcp_rn(A11);

    #pragma unroll
    for (int u = 0; u < 2; u++) {
        int idx = idx0 + u;
        int hh  = h + u;
        float gi = gp[hh];
        float gj = gp[KD + hh];
        float gf = gp[2 * KD + hh];
        float go = gp[3 * KD + hh];

        float fg = qvalf_r(1.0f / (1.0f + expf(-gf)), A3, R3);
        float ig = qvalf_r(1.0f / (1.0f + expf(-gi)), A4, R4);
        float ac = qvalf_r(tanhf(gj),                 A5, R5);
        float og = qvalf_r(1.0f / (1.0f + expf(-go)), A6, R6);

        float gc = qvalf_r(cx[idx] * fg, A7, R7);
        float ai = qvalf_r(ig * ac,      A8, R8);
        float nc = qvalf_r(gc + ai,      A9, R9);
        float tc = qvalf_r(tanhf(nc),    A10, R10);
        float nh = qvalf_r(tc * og,      A11, R11);

        out[idx]         = nh;  // new_h
        out[total + idx] = nc;  // new_c
    }
}

// ---------------- launcher ----------------
extern "C" void kernel_launch(void* const* d_in, const int* in_sizes, int n_in,
                              void* d_out, int out_size)
{
    const float* input = (const float*)d_in[0];
    const float* hx    = (const float*)d_in[1];
    const float* cx    = (const float*)d_in[2];
    const float* wmask = (const float*)d_in[3];
    const float* wih   = (const float*)d_in[4];
    const float* whh   = (const float*)d_in[5];
    const float* bih   = (const float*)d_in[6];
    const float* bhh   = (const float*)d_in[7];
    const float* a1  = (const float*)d_in[8];
    const float* a3  = (const float*)d_in[9];
    const float* a4  = (const float*)d_in[10];
    const float* a5  = (const float*)d_in[11];
    const float* a6  = (const float*)d_in[12];
    const float* a7  = (const float*)d_in[13];
    const float* a8  = (const float*)d_in[14];
    const float* a9  = (const float*)d_in[15];
    const float* a10 = (const float*)d_in[16];
    const float* a11 = (const float*)d_in[17];
    const float* a12 = (const float*)d_in[18];
    const float* a13 = (const float*)d_in[19];
    const float* a14 = (const float*)d_in[20];
    float* out = (float*)d_out;

    k_qact<<<(NBLK * NBATCH * KD / 4 + 255) / 256, 256>>>(input, hx, a1, a11);

    dim3 gg(NO / 32, 1, NBLK);
    k_gemm<<<gg, 256>>>(wih, whh, wmask, bih, bhh, a1, a11, a12, a13, a14);

    k_lstm<<<(NBLK * NBATCH * KD / 2 + 255) / 256, 256>>>(
        cx, out, a3, a4, a5, a6, a7, a8, a9, a10, a11);
}